// round 9
// baseline (speedup 1.0000x reference)
#include <cuda_runtime.h>
#include <math.h>

#define Bc 256
#define FEWc 5
#define Mc 200
#define Dc 100
#define Hc 450
#define NSYMc 70000
#define HP 464
#define NP 1856

__device__ __align__(16) float d_P[(NSYMc + 1) * 200];
__device__ __align__(16) float d_W2[200 * 100];
__device__ __align__(16) float d_x[FEWc * Bc * 200];
__device__ __align__(16) float d_XW0[FEWc * Bc * 3600];
__device__ __align__(16) float d_XW1[FEWc * Bc * 3600];
__device__ __align__(16) float d_y0[FEWc * Bc * 900];
__device__ __align__(16) float d_y1[FEWc * Bc * 900];
__device__ __align__(16) float d_hA[2 * Bc * HP];
__device__ __align__(16) float d_hB[2 * Bc * HP];
__device__ __align__(16) float d_cst[2 * Bc * Hc];
__device__ __align__(16) float d_Wih0i[2 * 1800 * 200];
__device__ __align__(16) float d_Wih1i[2 * 1800 * 900];
__device__ __align__(16) float d_Whh0i[2 * NP * HP];
__device__ __align__(16) float d_Whh1i[2 * NP * HP];
__device__ __align__(16) float d_bs0[2 * 1800];
__device__ __align__(16) float d_bs1[2 * 1800];
__device__ __align__(16) float d_finals[4 * Bc * Hc];
__device__ __align__(16) float d_rel[Bc * Dc];
__device__ __align__(16) float d_relq[Bc * Dc];
__device__ __align__(16) float d_normq[Bc * Dc];

__device__ __forceinline__ float sigm(float x) { return 1.0f / (1.0f + expf(-x)); }
__device__ __forceinline__ float warpred(float v) {
    for (int o = 16; o > 0; o >>= 1) v += __shfl_xor_sync(0xffffffff, v, o);
    return v;
}

// ====== double-buffered pipelined NT SGEMM: C[m][n]=sum_k A[m][k]*B[n][k] ===
template <int BM, int BN, int BK, int TM, int TN, bool GUARD>
__global__ __launch_bounds__(256, 2) void sgemm_nt(
    int M, int N, int K, int T,
    const float* __restrict__ A, int lda, long long sA,
    const float* __restrict__ Bm, int ldb, long long sB,
    float* __restrict__ C, int ldc, long long sC)
{
    constexpr int TX = BN / TN, TY = BM / TM;
    static_assert(TX * TY == 256, "");
    constexpr int KV = BK / 4;
    constexpr int NVA = BM * BK / 1024, NVB = BN * BK / 1024;
    __shared__ float As[2][BK][BM + 4];
    __shared__ float Bs[2][BK][BN + 4];
    A  += (long long)blockIdx.z * sA;
    Bm += (long long)blockIdx.z * sB;
    C  += (long long)blockIdx.z * sC;
    const int tid = threadIdx.x, tx = tid % TX, ty = tid / TX;
    const int m0 = blockIdx.y * BM, n0 = blockIdx.x * BN;
    const float4 z4 = make_float4(0.f, 0.f, 0.f, 0.f);

    float4 aR[NVA], bR[NVB];
#pragma unroll
    for (int v = 0; v < NVA; v++) {
        int idx = tid + v * 256, r = idx / KV, kv = idx % KV;
        int gm = m0 + r, gk = kv * 4;
        aR[v] = (!GUARD || (gm < M && gk < K)) ? *(const float4*)(A + (long long)gm * lda + gk) : z4;
    }
#pragma unroll
    for (int v = 0; v < NVB; v++) {
        int idx = tid + v * 256, r = idx / KV, kv = idx % KV;
        int gn = n0 + r, gk = kv * 4;
        bR[v] = (!GUARD || (gn < N && gk < K)) ? *(const float4*)(Bm + (long long)gn * ldb + gk) : z4;
    }
    // store tile 0 into buffer 0
#pragma unroll
    for (int v = 0; v < NVA; v++) {
        int idx = tid + v * 256, r = idx / KV, kv = idx % KV;
        As[0][kv * 4 + 0][r] = aR[v].x; As[0][kv * 4 + 1][r] = aR[v].y;
        As[0][kv * 4 + 2][r] = aR[v].z; As[0][kv * 4 + 3][r] = aR[v].w;
    }
#pragma unroll
    for (int v = 0; v < NVB; v++) {
        int idx = tid + v * 256, r = idx / KV, kv = idx % KV;
        Bs[0][kv * 4 + 0][r] = bR[v].x; Bs[0][kv * 4 + 1][r] = bR[v].y;
        Bs[0][kv * 4 + 2][r] = bR[v].z; Bs[0][kv * 4 + 3][r] = bR[v].w;
    }
    __syncthreads();

    unsigned long long acc2[TM][TN / 2];
#pragma unroll
    for (int i = 0; i < TM; i++)
#pragma unroll
        for (int j = 0; j < TN / 2; j++) acc2[i][j] = 0ull;

    for (int t = 0; t < T; t++) {
        const int cur = t & 1, nxt = cur ^ 1;
        if (t + 1 < T) {
            int k0 = (t + 1) * BK;
#pragma unroll
            for (int v = 0; v < NVA; v++) {
                int idx = tid + v * 256, r = idx / KV, kv = idx % KV;
                int gm = m0 + r, gk = k0 + kv * 4;
                aR[v] = (!GUARD || (gm < M && gk < K)) ? *(const float4*)(A + (long long)gm * lda + gk) : z4;
            }
#pragma unroll
            for (int v = 0; v < NVB; v++) {
                int idx = tid + v * 256, r = idx / KV, kv = idx % KV;
                int gn = n0 + r, gk = k0 + kv * 4;
                bR[v] = (!GUARD || (gn < N && gk < K)) ? *(const float4*)(Bm + (long long)gn * ldb + gk) : z4;
            }
        }
#pragma unroll
        for (int kk = 0; kk < BK; kk++) {
            float4 raV[TM / 4];
#pragma unroll
            for (int i = 0; i < TM / 4; i++)
                raV[i] = *(const float4*)&As[cur][kk][ty * TM + 4 * i];
            const float* ra = (const float*)raV;
            float4 rbV[TN / 4];
#pragma unroll
            for (int j = 0; j < TN / 4; j++)
                rbV[j] = *(const float4*)&Bs[cur][kk][tx * TN + 4 * j];
            const unsigned long long* rb = (const unsigned long long*)rbV;
#pragma unroll
            for (int i = 0; i < TM; i++) {
                unsigned long long a2;
                unsigned au = __float_as_uint(ra[i]);
                asm("mov.b64 %0,{%1,%1};" : "=l"(a2) : "r"(au));
#pragma unroll
                for (int j = 0; j < TN / 2; j++)
                    asm("fma.rn.f32x2 %0,%1,%2,%3;"
                        : "=l"(acc2[i][j]) : "l"(a2), "l"(rb[j]), "l"(acc2[i][j]));
            }
        }
        if (t + 1 < T) {
#pragma unroll
            for (int v = 0; v < NVA; v++) {
                int idx = tid + v * 256, r = idx / KV, kv = idx % KV;
                As[nxt][kv * 4 + 0][r] = aR[v].x; As[nxt][kv * 4 + 1][r] = aR[v].y;
                As[nxt][kv * 4 + 2][r] = aR[v].z; As[nxt][kv * 4 + 3][r] = aR[v].w;
            }
#pragma unroll
            for (int v = 0; v < NVB; v++) {
                int idx = tid + v * 256, r = idx / KV, kv = idx % KV;
                Bs[nxt][kv * 4 + 0][r] = bR[v].x; Bs[nxt][kv * 4 + 1][r] = bR[v].y;
                Bs[nxt][kv * 4 + 2][r] = bR[v].z; Bs[nxt][kv * 4 + 3][r] = bR[v].w;
            }
            __syncthreads();
        }
    }
#pragma unroll
    for (int i = 0; i < TM; i++) {
        int m = m0 + ty * TM + i;
        if (m >= M) continue;
#pragma unroll
        for (int j = 0; j < TN / 2; j++) {
            union { unsigned long long u; float f[2]; } cv;
            cv.u = acc2[i][j];
            int n = n0 + tx * TN + 2 * j;
            if (n + 1 < N) *(float2*)(C + (long long)m * ldc + n) = make_float2(cv.f[0], cv.f[1]);
            else if (n < N) C[(long long)m * ldc + n] = cv.f[0];
        }
    }
}

// ====== fused recurrent GEMM + LSTM cell (R6 tiling + double buffer) =======
// BM=BN=64, TM=TN=4; grid (29, 4, 2) = 232 blocks.
__global__ __launch_bounds__(256) void lstm_rec(
    const float* __restrict__ h_in, const float* __restrict__ Whh,
    const float* __restrict__ XW, const float* __restrict__ bs,
    float* __restrict__ h_out, float* __restrict__ c,
    float* __restrict__ y, int step, int finalsBase)
{
    constexpr int BK = 16, KV = 4;
    __shared__ float As[2][BK][68];
    __shared__ float Bs[2][BK][68];
    const int dir = blockIdx.z;
    const float* A  = h_in + (long long)dir * Bc * HP;
    const float* Bm = Whh + (long long)dir * NP * HP;
    const int tid = threadIdx.x, tx = tid % 16, ty = tid / 16;
    const int m0 = blockIdx.y * 64, n0 = blockIdx.x * 64;
    const int T = HP / BK;
    const int r = tid / KV, kv = tid % KV;

    float4 aR = *(const float4*)(A + (long long)(m0 + r) * HP + kv * 4);
    float4 bR = *(const float4*)(Bm + (long long)(n0 + r) * HP + kv * 4);
    As[0][kv * 4 + 0][r] = aR.x; As[0][kv * 4 + 1][r] = aR.y;
    As[0][kv * 4 + 2][r] = aR.z; As[0][kv * 4 + 3][r] = aR.w;
    Bs[0][kv * 4 + 0][r] = bR.x; Bs[0][kv * 4 + 1][r] = bR.y;
    Bs[0][kv * 4 + 2][r] = bR.z; Bs[0][kv * 4 + 3][r] = bR.w;
    __syncthreads();

    unsigned long long acc2[4][2];
#pragma unroll
    for (int i = 0; i < 4; i++) { acc2[i][0] = 0ull; acc2[i][1] = 0ull; }

    for (int t = 0; t < T; t++) {
        const int cur = t & 1, nxt = cur ^ 1;
        if (t + 1 < T) {
            int gk = (t + 1) * BK + kv * 4;
            aR = *(const float4*)(A + (long long)(m0 + r) * HP + gk);
            bR = *(const float4*)(Bm + (long long)(n0 + r) * HP + gk);
        }
#pragma unroll
        for (int kk = 0; kk < BK; kk++) {
            float4 raV = *(const float4*)&As[cur][kk][ty * 4];
            const float* ra = (const float*)&raV;
            float4 rbV = *(const float4*)&Bs[cur][kk][tx * 4];
            const unsigned long long* rb = (const unsigned long long*)&rbV;
#pragma unroll
            for (int i = 0; i < 4; i++) {
                unsigned long long a2;
                unsigned au = __float_as_uint(ra[i]);
                asm("mov.b64 %0,{%1,%1};" : "=l"(a2) : "r"(au));
                asm("fma.rn.f32x2 %0,%1,%2,%3;" : "=l"(acc2[i][0]) : "l"(a2), "l"(rb[0]), "l"(acc2[i][0]));
                asm("fma.rn.f32x2 %0,%1,%2,%3;" : "=l"(acc2[i][1]) : "l"(a2), "l"(rb[1]), "l"(acc2[i][1]));
            }
        }
        if (t + 1 < T) {
            As[nxt][kv * 4 + 0][r] = aR.x; As[nxt][kv * 4 + 1][r] = aR.y;
            As[nxt][kv * 4 + 2][r] = aR.z; As[nxt][kv * 4 + 3][r] = aR.w;
            Bs[nxt][kv * 4 + 0][r] = bR.x; Bs[nxt][kv * 4 + 1][r] = bR.y;
            Bs[nxt][kv * 4 + 2][r] = bR.z; Bs[nxt][kv * 4 + 3][r] = bR.w;
            __syncthreads();
        }
    }

    // epilogue: columns n0+tx*4 .. +3 = 4 gates of unit jj
    const int jj = (n0 >> 2) + tx;
    if (jj >= Hc) return;
    const int tstep = dir ? (4 - step) : step;
    const float4 bsv = *(const float4*)(bs + dir * 1800 + 4 * jj);
#pragma unroll
    for (int i = 0; i < 4; i++) {
        int b = m0 + ty * 4 + i;
        union { unsigned long long u; float f[2]; } c0, c1;
        c0.u = acc2[i][0]; c1.u = acc2[i][1];
        const float4 xwv = *(const float4*)(XW + ((long long)(tstep * Bc + b)) * 3600 + dir * 1800 + 4 * jj);
        float gi = c0.f[0] + xwv.x + bsv.x;
        float gf = c0.f[1] + xwv.y + bsv.y;
        float gg = c1.f[0] + xwv.z + bsv.z;
        float go = c1.f[1] + xwv.w + bsv.w;
        int ci = (dir * Bc + b) * Hc + jj;
        float cp = c[ci];
        float cn = sigm(gf) * cp + sigm(gi) * tanhf(gg);
        float hn = sigm(go) * tanhf(cn);
        c[ci] = cn;
        h_out[(dir * Bc + b) * HP + jj] = hn;
        y[((long long)(tstep * Bc + b)) * 900 + dir * Hc + jj] = hn;
        if (step == 4) d_finals[((long long)(finalsBase + dir) * Bc + b) * Hc + jj] = hn;
    }
}

// ============ step 0 (no recurrent term) ===================================
__global__ void lstm_step0(const float* __restrict__ XW, const float* __restrict__ bs,
                           float* __restrict__ h_out, float* __restrict__ c,
                           float* __restrict__ y)
{
    int idx = blockIdx.x * blockDim.x + threadIdx.x;
    if (idx >= 2 * Bc * Hc) return;
    int dir = idx / (Bc * Hc);
    int r = idx - dir * Bc * Hc;
    int b = r / Hc, j = r - (r / Hc) * Hc;
    int t = dir ? 4 : 0;
    const float4 xwv = *(const float4*)(XW + ((long long)(t * Bc + b)) * 3600 + dir * 1800 + 4 * j);
    const float4 bsv = *(const float4*)(bs + dir * 1800 + 4 * j);
    float gi = xwv.x + bsv.x, gg = xwv.z + bsv.z, go = xwv.w + bsv.w;
    float cn = sigm(gi) * tanhf(gg);
    float hn = sigm(go) * tanhf(cn);
    c[(dir * Bc + b) * Hc + j] = cn;
    h_out[(dir * Bc + b) * HP + j] = hn;
    y[((long long)(t * Bc + b)) * 900 + dir * Hc + j] = hn;
}

// ============ prep kernels =================================================
__global__ void prep_small(const float* __restrict__ gcn_w,
                           const float* __restrict__ bih0, const float* __restrict__ bhh0,
                           const float* __restrict__ bih1, const float* __restrict__ bhh1)
{
    int i = blockIdx.x * blockDim.x + threadIdx.x;
    if (i < 20000) {
        int op = i / 100, k = i - op * 100;
        d_W2[op * 100 + k] = gcn_w[(op % 100) * 200 + (op / 100) * 100 + k];
    } else if (i < 23600) {
        int r = i - 20000, dir = r / 1800, q = r - dir * 1800;
        int j = q >> 2, g = q & 3, s = dir * 1800 + g * 450 + j;
        d_bs0[dir * 1800 + q] = bih0[s] + bhh0[s];
    } else if (i < 27200) {
        int r = i - 23600, dir = r / 1800, q = r - dir * 1800;
        int j = q >> 2, g = q & 3, s = dir * 1800 + g * 450 + j;
        d_bs1[dir * 1800 + q] = bih1[s] + bhh1[s];
    } else if (i < 27200 + 2 * Bc * HP) {
        d_hA[i - 27200] = 0.0f;
    } else if (i < 27200 + 4 * Bc * HP) {
        d_hB[i - 27200 - 2 * Bc * HP] = 0.0f;
    }
}

__global__ void prep_ih(const float* __restrict__ Wih0, const float* __restrict__ Wih1)
{
    int i = blockIdx.x * blockDim.x + threadIdx.x;
    if (i < 720000) {
        int dir = i / 360000, rem = i - dir * 360000;
        int q = rem / 200, k = rem - q * 200;
        int j = q >> 2, g = q & 3;
        d_Wih0i[i] = Wih0[dir * 360000 + (g * 450 + j) * 200 + k];
    } else if (i < 720000 + 3240000) {
        int i2 = i - 720000;
        int dir = i2 / 1620000, rem = i2 - dir * 1620000;
        int q = rem / 900, k = rem - q * 900;
        int j = q >> 2, g = q & 3;
        d_Wih1i[i2] = Wih1[dir * 1620000 + (g * 450 + j) * 900 + k];
    }
}

__global__ void prep_hh(const float* __restrict__ Whh0, const float* __restrict__ Whh1)
{
    int i = blockIdx.x * blockDim.x + threadIdx.x;
    const int PER = 2 * NP * HP;
    if (i >= 2 * PER) return;
    int layer = i / PER, i2 = i - layer * PER;
    int dir = i2 / (NP * HP), rem = i2 - dir * (NP * HP);
    int r = rem / HP, k = rem - r * HP;
    float v = 0.0f;
    if (r < 1800 && k < 450) {
        int j = r >> 2, g = r & 3;
        const float* src = layer ? Whh1 : Whh0;
        v = src[dir * 810000 + (g * 450 + j) * 450 + k];
    }
    (layer ? d_Whh1i : d_Whh0i)[i2] = v;
}

// ============ neighbor encoder (1 block per row) ===========================
__global__ __launch_bounds__(256) void encoder_kernel(
    const int* __restrict__ lc, const int* __restrict__ rc,
    const float* __restrict__ emb,
    const float* __restrict__ gcn_wb, const float* __restrict__ gcn_b,
    const float* __restrict__ attn_w, const float* __restrict__ attn_wb,
    const float* __restrict__ gate_w, const float* __restrict__ gate_wb,
    const float* __restrict__ gate_b)
{
    extern __shared__ __align__(16) float outbuf[];
    __shared__ float logits[Mc], wts[Mc], bias[Dc], aw[Dc], gw[Dc], oattn[Dc], red[256], gsc;
    const int n = blockIdx.x;
    const int f = n / (2 * Bc);
    const int rem = n - f * 2 * Bc;
    const int s = rem / Bc, bb = rem - (rem / Bc) * Bc;
    const int* conn = (s == 0 ? lc : rc) + ((long long)(f * Bc + bb) * Mc) * 3;
    const int tid = threadIdx.x;
    if (tid < Dc) { bias[tid] = gcn_wb[tid] + gcn_b[tid]; aw[tid] = attn_w[tid]; gw[tid] = gate_w[tid]; }
    __syncthreads();
    const float awb = attn_wb[0];

    for (int m = tid; m < Mc; m += 256) {
        int i1 = conn[m * 3 + 1], i2 = conn[m * 3 + 2];
        const float4* p1 = (const float4*)(d_P + (long long)i1 * 200);
        const float4* p2 = (const float4*)(d_P + (long long)i2 * 200 + 100);
        float4* orow = (float4*)(outbuf + m * Dc);
        float lg = 0.0f;
#pragma unroll 25
        for (int q = 0; q < 25; q++) {
            float4 a = p1[q], b4 = p2[q];
            float v0 = a.x + b4.x + bias[4 * q + 0];
            float v1 = a.y + b4.y + bias[4 * q + 1];
            float v2 = a.z + b4.z + bias[4 * q + 2];
            float v3 = a.w + b4.w + bias[4 * q + 3];
            v0 = v0 >= 0.f ? v0 : 0.01f * v0;
            v1 = v1 >= 0.f ? v1 : 0.01f * v1;
            v2 = v2 >= 0.f ? v2 : 0.01f * v2;
            v3 = v3 >= 0.f ? v3 : 0.01f * v3;
            float4 o; o.x = v0; o.y = v1; o.z = v2; o.w = v3;
            orow[q] = o;
            lg += v0 * aw[4 * q] + v1 * aw[4 * q + 1] + v2 * aw[4 * q + 2] + v3 * aw[4 * q + 3];
        }
        logits[m] = lg + awb;
    }
    __syncthreads();

    float lm = -1e30f;
    for (int m = tid; m < Mc; m += 256) lm = fmaxf(lm, logits[m]);
    red[tid] = lm; __syncthreads();
    for (int st = 128; st > 0; st >>= 1) { if (tid < st) red[tid] = fmaxf(red[tid], red[tid + st]); __syncthreads(); }
    float mx = red[0]; __syncthreads();
    float ls = 0.0f;
    for (int m = tid; m < Mc; m += 256) { float e = expf(logits[m] - mx); wts[m] = e; ls += e; }
    red[tid] = ls; __syncthreads();
    for (int st = 128; st > 0; st >>= 1) { if (tid < st) red[tid] += red[tid + st]; __syncthreads(); }
    float inv = 1.0f / red[0]; __syncthreads();
    for (int m = tid; m < Mc; m += 256) wts[m] *= inv;
    __syncthreads();

    for (int o = tid; o < Dc; o += 256) {
        float acc = 0.0f;
        for (int m = 0; m < Mc; m++) acc += outbuf[m * Dc + o] * wts[m];
        oattn[o] = acc;
    }
    __syncthreads();

    float gd = 0.0f;
    for (int o = tid; o < Dc; o += 256) gd += oattn[o] * gw[o];
    red[tid] = gd; __syncthreads();
    for (int st = 128; st > 0; st >>= 1) { if (tid < st) red[tid] += red[tid + st]; __syncthreads(); }
    if (tid == 0) gsc = sigm(red[0] + gate_wb[0] + gate_b[0]);
    __syncthreads();
    float g = gsc;
    int self_idx = conn[0];
    const float* se = emb + (long long)self_idx * Dc;
    for (int o = tid; o < Dc; o += 256)
        d_x[((long long)f * Bc + bb) * 200 + s * Dc + o] = oattn[o] * g + se[o] * (1.0f - g);
}

// ============ attention over LSTM output + rel projection ==================
__global__ __launch_bounds__(256) void attn_kernel(const float* __restrict__ out_w,
                                                   const float* __restrict__ out_b)
{
    __shared__ float O[FEWc * 900];
    __shared__ float Hs[1800], ctx[1800], lg[10], awt[10];
    const int b = blockIdx.x, tid = threadIdx.x;
    for (int i = tid; i < FEWc * 900; i += 256) {
        int t = i / 900, h2 = i - t * 900;
        O[i] = d_y1[((long long)t * Bc + b) * 900 + h2];
    }
    for (int i = tid; i < 1800; i += 256) Hs[i] = d_finals[(long long)b * 1800 + i];
    if (tid < 10) lg[tid] = 0.0f;
    __syncthreads();

    float part[10];
#pragma unroll
    for (int q = 0; q < 10; q++) part[q] = 0.0f;
    for (int h2 = tid; h2 < 900; h2 += 256) {
        float hl0 = Hs[2 * h2], hl1 = Hs[2 * h2 + 1];
#pragma unroll
        for (int t = 0; t < 5; t++) {
            float ov = O[t * 900 + h2];
            part[2 * t]     += ov * hl0;
            part[2 * t + 1] += ov * hl1;
        }
    }
#pragma unroll
    for (int q = 0; q < 10; q++) {
        float v = warpred(part[q]);
        if ((tid & 31) == 0) atomicAdd(&lg[q], v);
    }
    __syncthreads();
    if (tid < 2) {
        int l = tid;
        float mxv = -1e30f;
        for (int t = 0; t < 5; t++) mxv = fmaxf(mxv, lg[t * 2 + l]);
        float sm = 0.0f, e[5];
        for (int t = 0; t < 5; t++) { e[t] = expf(lg[t * 2 + l] - mxv); sm += e[t]; }
        for (int t = 0; t < 5; t++) awt[t * 2 + l] = e[t] / sm;
    }
    __syncthreads();
    for (int i = tid; i < 1800; i += 256) {
        int h2 = i >> 1, l = i & 1;
        float acc = 0.0f;
#pragma unroll
        for (int t = 0; t < 5; t++) acc += O[t * 900 + h2] * awt[t * 2 + l];
        ctx[i] = acc;
    }
    __syncthreads();
    int w = tid >> 5, lane = tid & 31;
    for (int o = w; o < Dc; o += 8) {
        float acc = 0.0f;
        for (int k = lane; k < 1800; k += 32) acc += ctx[k] * out_w[(long long)o * 1800 + k];
        acc = warpred(acc);
        if (lane == 0) d_rel[(long long)b * Dc + o] = acc + out_b[o];
    }
}

// ============ meta gradient ================================================
__global__ void meta_kernel(const float* __restrict__ support, const float* __restrict__ sneg,
                            const float* __restrict__ normv)
{
    int b = blockIdx.x, lane = threadIdx.x;
    float r4[4], n4[4], g4[4] = {0, 0, 0, 0};
#pragma unroll
    for (int i = 0; i < 4; i++) {
        int o = lane + 32 * i;
        r4[i] = (o < Dc) ? d_rel[b * Dc + o] : 0.0f;
        n4[i] = (o < Dc) ? normv[(long long)b * Dc + o] : 0.0f;
    }
    for (int k = 0; k < 5; k++) {
        const float* hp = support + ((long long)(b * 5 + k) * 2) * Dc;
        const float* tp = hp + Dc;
        const float* hn = sneg + ((long long)(b * 5 + k) * 2) * Dc;
        const float* tn = hn + Dc;
        float up[4], un[4], ap = 0.0f, an = 0.0f;
#pragma unroll
        for (int i = 0; i < 4; i++) {
            int o = lane + 32 * i;
            up[i] = (o < Dc) ? hp[o] - tp[o] : 0.0f;
            un[i] = (o < Dc) ? hn[o] - tn[o] : 0.0f;
            ap += up[i] * n4[i];
            an += un[i] * n4[i];
        }
        ap = warpred(ap); an = warpred(an);
        float dp4[4], dn4[4], sp = 0.0f, sn = 0.0f;
#pragma unroll
        for (int i = 0; i < 4; i++) {
            dp4[i] = up[i] + r4[i] - ap * n4[i];
            dn4[i] = un[i] + r4[i] - an * n4[i];
            sp += dp4[i] * dp4[i];
            sn += dn4[i] * dn4[i];
        }
        sp = warpred(sp); sn = warpred(sn);
        float Dp = sqrtf(sp), Dn = sqrtf(sn);
        if (1.0f + Dp - Dn > 0.0f) {
            float ip = 1.0f / Dp, inn = 1.0f / Dn;
#pragma unroll
            for (int i = 0; i < 4; i++) g4[i] += dp4[i] * ip - dn4[i] * inn;
        }
    }
#pragma unroll
    for (int i = 0; i < 4; i++) {
        int o = lane + 32 * i;
        if (o < Dc) {
            float g = g4[i] * (1.0f / 1280.0f);
            d_relq[b * Dc + o]  = r4[i] - 5.0f * g;
            d_normq[b * Dc + o] = n4[i] - 5.0f * g;
        }
    }
}

// ============ final scoring ================================================
__global__ __launch_bounds__(256) void score_kernel(const float* __restrict__ query,
                                                    const float* __restrict__ negative,
                                                    float* __restrict__ out)
{
    __shared__ float rq[Dc], nq[Dc];
    int b = blockIdx.y, tid = threadIdx.x;
    if (tid < Dc) { rq[tid] = d_relq[b * Dc + tid]; nq[tid] = d_normq[b * Dc + tid]; }
    __syncthreads();
    int w = tid >> 5, lane = tid & 31;
    int q = blockIdx.x * 8 + w;
    if (q >= 522) return;
    const float* hp;
    if (q < 10) hp = query + ((long long)(b * 10 + q) * 2) * Dc;
    else        hp = negative + ((long long)(b * 512 + (q - 10)) * 2) * Dc;
    const float* tp = hp + Dc;
    float u[4], rr[4], nn2[4], al = 0.0f;
#pragma unroll
    for (int i = 0; i < 4; i++) {
        int o = lane + 32 * i;
        if (o < Dc) { u[i] = hp[o] - tp[o]; rr[i] = rq[o]; nn2[i] = nq[o]; }
        else        { u[i] = 0.0f; rr[i] = 0.0f; nn2[i] = 0.0f; }
        al += u[i] * nn2[i];
    }
    al = warpred(al);
    float s = 0.0f;
#pragma unroll
    for (int i = 0; i < 4; i++) {
        float d = u[i] + rr[i] - al * nn2[i];
        s += d * d;
    }
    s = warpred(s);
    if (lane == 0) {
        float sc = -sqrtf(s);
        if (q < 10) out[b * 10 + q] = sc;
        else        out[2560 + (long long)b * 512 + (q - 10)] = sc;
    }
}

// ============ host launcher ================================================
extern "C" void kernel_launch(void* const* d_in, const int* in_sizes, int n_in,
                              void* d_out, int out_size)
{
    const float* support  = (const float*)d_in[0];
    const float* sneg     = (const float*)d_in[1];
    const float* query    = (const float*)d_in[2];
    const float* negative = (const float*)d_in[3];
    const float* normv    = (const float*)d_in[4];
    const int*   leftc    = (const int*)d_in[5];
    const int*   rightc   = (const int*)d_in[6];
    const float* emb      = (const float*)d_in[7];
    const float* gcn_w    = (const float*)d_in[8];
    const float* gcn_wb   = (const float*)d_in[9];
    const float* gcn_b    = (const float*)d_in[10];
    const float* attn_w   = (const float*)d_in[11];
    const float* attn_wb  = (const float*)d_in[12];
    const float* gate_w   = (const float*)d_in[13];
    const float* gate_wb  = (const float*)d_in[14];
    const float* gate_b   = (const float*)d_in[15];
    const float* Wih0     = (const float*)d_in[16];
    const float* Whh0     = (const float*)d_in[17];
    const float* bih0     = (const float*)d_in[18];
    const float* bhh0     = (const float*)d_in[19];
    const float* Wih1     = (const float*)d_in[20];
    const float* Whh1     = (const float*)d_in[21];
    const float* bih1     = (const float*)d_in[22];
    const float* bhh1     = (const float*)d_in[23];
    const float* out_w    = (const float*)d_in[24];
    const float* out_b    = (const float*)d_in[25];
    float* out = (float*)d_out;

    float *P, *W2, *X, *XW0v, *XW1v, *Y0, *Y1, *HA, *HB, *Cst;
    float *Wih0i, *Wih1i, *Whh0i, *Whh1i, *BS0, *BS1;
    cudaGetSymbolAddress((void**)&P,     d_P);
    cudaGetSymbolAddress((void**)&W2,    d_W2);
    cudaGetSymbolAddress((void**)&X,     d_x);
    cudaGetSymbolAddress((void**)&XW0v,  d_XW0);
    cudaGetSymbolAddress((void**)&XW1v,  d_XW1);
    cudaGetSymbolAddress((void**)&Y0,    d_y0);
    cudaGetSymbolAddress((void**)&Y1,    d_y1);
    cudaGetSymbolAddress((void**)&HA,    d_hA);
    cudaGetSymbolAddress((void**)&HB,    d_hB);
    cudaGetSymbolAddress((void**)&Cst,   d_cst);
    cudaGetSymbolAddress((void**)&Wih0i, d_Wih0i);
    cudaGetSymbolAddress((void**)&Wih1i, d_Wih1i);
    cudaGetSymbolAddress((void**)&Whh0i, d_Whh0i);
    cudaGetSymbolAddress((void**)&Whh1i, d_Whh1i);
    cudaGetSymbolAddress((void**)&BS0,   d_bs0);
    cudaGetSymbolAddress((void**)&BS1,   d_bs1);

    int prepN = 27200 + 4 * Bc * HP;
    prep_small<<<(prepN + 255) / 256, 256>>>(gcn_w, bih0, bhh0, bih1, bhh1);
    prep_ih<<<(3960000 + 255) / 256, 256>>>(Wih0, Wih1);
    prep_hh<<<(2 * 2 * NP * HP + 255) / 256, 256>>>(Whh0, Whh1);

    // P = emb @ W2^T
    {
        dim3 g(2, (NSYMc + 1 + 127) / 128, 1);
        sgemm_nt<128, 128, 16, 8, 8, true><<<g, 256>>>(NSYMc + 1, 200, 100, 7,
            emb, 100, 0, W2, 100, 0, P, 200, 0);
    }
    cudaFuncSetAttribute(encoder_kernel, cudaFuncAttributeMaxDynamicSharedMemorySize,
                         Mc * Dc * (int)sizeof(float));
    encoder_kernel<<<FEWc * 2 * Bc, 256, Mc * Dc * sizeof(float)>>>(
        leftc, rightc, emb, gcn_wb, gcn_b, attn_w, attn_wb, gate_w, gate_wb, gate_b);

    dim3 gbig(15, 10, 2);
    dim3 grec(29, 4, 2);

    // layer 0
    sgemm_nt<128, 128, 16, 8, 8, true><<<gbig, 256>>>(FEWc * Bc, 1800, 200, 13,
        X, 200, 0, Wih0i, 200, (long long)1800 * 200, XW0v, 3600, 1800);
    lstm_step0<<<900, 256>>>(XW0v, BS0, HA, Cst, Y0);
    float* hbuf[2] = {HA, HB};
    for (int s = 1; s < 5; s++)
        lstm_rec<<<grec, 256>>>(hbuf[(s + 1) & 1], Whh0i, XW0v, BS0, hbuf[s & 1], Cst, Y0, s, 0);
    // layer 1
    sgemm_nt<128, 128, 16, 8, 8, true><<<gbig, 256>>>(FEWc * Bc, 1800, 900, 57,
        Y0, 900, 0, Wih1i, 900, (long long)1800 * 900, XW1v, 3600, 1800);
    lstm_step0<<<900, 256>>>(XW1v, BS1, HA, Cst, Y1);
    for (int s = 1; s < 5; s++)
        lstm_rec<<<grec, 256>>>(hbuf[(s + 1) & 1], Whh1i, XW1v, BS1, hbuf[s & 1], Cst, Y1, s, 2);

    attn_kernel<<<Bc, 256>>>(out_w, out_b);
    meta_kernel<<<Bc, 32>>>(support, sneg, normv);
    score_kernel<<<dim3((522 + 7) / 8, Bc), 256>>>(query, negative, out);
}

// round 10
// speedup vs baseline: 1.6194x; 1.6194x over previous
#include <cuda_runtime.h>
#include <math.h>

#define Bc 256
#define FEWc 5
#define Mc 200
#define Dc 100
#define Hc 450
#define NSYMc 70000
#define HP 464
#define NP 1856

__device__ __align__(16) float d_P[(NSYMc + 1) * 200];
__device__ __align__(16) float d_W2[200 * 100];
__device__ __align__(16) float d_x[FEWc * Bc * 200];
__device__ __align__(16) float d_XW0[FEWc * Bc * 3600];
__device__ __align__(16) float d_XW1[FEWc * Bc * 3600];
__device__ __align__(16) float d_y0[FEWc * Bc * 900];
__device__ __align__(16) float d_y1[FEWc * Bc * 900];
__device__ __align__(16) float d_hA[2 * Bc * HP];
__device__ __align__(16) float d_hB[2 * Bc * HP];
__device__ __align__(16) float d_cst[2 * Bc * Hc];
__device__ __align__(16) float d_Wih0i[2 * 1800 * 200];
__device__ __align__(16) float d_Wih1i[2 * 1800 * 900];
__device__ __align__(16) float d_Whh0i[2 * NP * HP];
__device__ __align__(16) float d_Whh1i[2 * NP * HP];
__device__ __align__(16) float d_bs0[2 * 1800];
__device__ __align__(16) float d_bs1[2 * 1800];
__device__ __align__(16) float d_finals[4 * Bc * Hc];
__device__ __align__(16) float d_rel[Bc * Dc];
__device__ __align__(16) float d_relq[Bc * Dc];
__device__ __align__(16) float d_normq[Bc * Dc];

__device__ __forceinline__ float sigm(float x) { return 1.0f / (1.0f + expf(-x)); }
__device__ __forceinline__ float warpred(float v) {
    for (int o = 16; o > 0; o >>= 1) v += __shfl_xor_sync(0xffffffff, v, o);
    return v;
}

// ====== single-buffer pipelined NT SGEMM (best-known config, R8) ===========
template <int BM, int BN, int BK, int TM, int TN, bool GUARD>
__global__ __launch_bounds__(256, 2) void sgemm_nt(
    int M, int N, int K, int T,
    const float* __restrict__ A, int lda, long long sA,
    const float* __restrict__ Bm, int ldb, long long sB,
    float* __restrict__ C, int ldc, long long sC)
{
    constexpr int TX = BN / TN, TY = BM / TM;
    static_assert(TX * TY == 256, "");
    constexpr int KV = BK / 4;
    constexpr int NVA = BM * BK / 1024, NVB = BN * BK / 1024;
    __shared__ float As[BK][BM + 4];
    __shared__ float Bs[BK][BN + 4];
    A  += (long long)blockIdx.z * sA;
    Bm += (long long)blockIdx.z * sB;
    C  += (long long)blockIdx.z * sC;
    const int tid = threadIdx.x, tx = tid % TX, ty = tid / TX;
    const int m0 = blockIdx.y * BM, n0 = blockIdx.x * BN;
    const float4 z4 = make_float4(0.f, 0.f, 0.f, 0.f);

    float4 aR[NVA], bR[NVB];
#pragma unroll
    for (int v = 0; v < NVA; v++) {
        int idx = tid + v * 256, r = idx / KV, kv = idx % KV;
        int gm = m0 + r, gk = kv * 4;
        aR[v] = (!GUARD || (gm < M && gk < K)) ? *(const float4*)(A + (long long)gm * lda + gk) : z4;
    }
#pragma unroll
    for (int v = 0; v < NVB; v++) {
        int idx = tid + v * 256, r = idx / KV, kv = idx % KV;
        int gn = n0 + r, gk = kv * 4;
        bR[v] = (!GUARD || (gn < N && gk < K)) ? *(const float4*)(Bm + (long long)gn * ldb + gk) : z4;
    }

    unsigned long long acc2[TM][TN / 2];
#pragma unroll
    for (int i = 0; i < TM; i++)
#pragma unroll
        for (int j = 0; j < TN / 2; j++) acc2[i][j] = 0ull;

    for (int t = 0; t < T; t++) {
#pragma unroll
        for (int v = 0; v < NVA; v++) {
            int idx = tid + v * 256, r = idx / KV, kv = idx % KV;
            As[kv * 4 + 0][r] = aR[v].x; As[kv * 4 + 1][r] = aR[v].y;
            As[kv * 4 + 2][r] = aR[v].z; As[kv * 4 + 3][r] = aR[v].w;
        }
#pragma unroll
        for (int v = 0; v < NVB; v++) {
            int idx = tid + v * 256, r = idx / KV, kv = idx % KV;
            Bs[kv * 4 + 0][r] = bR[v].x; Bs[kv * 4 + 1][r] = bR[v].y;
            Bs[kv * 4 + 2][r] = bR[v].z; Bs[kv * 4 + 3][r] = bR[v].w;
        }
        __syncthreads();
        if (t + 1 < T) {
            int k0 = (t + 1) * BK;
#pragma unroll
            for (int v = 0; v < NVA; v++) {
                int idx = tid + v * 256, r = idx / KV, kv = idx % KV;
                int gm = m0 + r, gk = k0 + kv * 4;
                aR[v] = (!GUARD || (gm < M && gk < K)) ? *(const float4*)(A + (long long)gm * lda + gk) : z4;
            }
#pragma unroll
            for (int v = 0; v < NVB; v++) {
                int idx = tid + v * 256, r = idx / KV, kv = idx % KV;
                int gn = n0 + r, gk = k0 + kv * 4;
                bR[v] = (!GUARD || (gn < N && gk < K)) ? *(const float4*)(Bm + (long long)gn * ldb + gk) : z4;
            }
        }
#pragma unroll
        for (int kk = 0; kk < BK; kk++) {
            float4 raV[TM / 4];
#pragma unroll
            for (int i = 0; i < TM / 4; i++)
                raV[i] = *(const float4*)&As[kk][ty * TM + 4 * i];
            const float* ra = (const float*)raV;
            float4 rbV[TN / 4];
#pragma unroll
            for (int j = 0; j < TN / 4; j++)
                rbV[j] = *(const float4*)&Bs[kk][tx * TN + 4 * j];
            const unsigned long long* rb = (const unsigned long long*)rbV;
#pragma unroll
            for (int i = 0; i < TM; i++) {
                unsigned long long a2;
                unsigned au = __float_as_uint(ra[i]);
                asm("mov.b64 %0,{%1,%1};" : "=l"(a2) : "r"(au));
#pragma unroll
                for (int j = 0; j < TN / 2; j++)
                    asm("fma.rn.f32x2 %0,%1,%2,%3;"
                        : "=l"(acc2[i][j]) : "l"(a2), "l"(rb[j]), "l"(acc2[i][j]));
            }
        }
        __syncthreads();
    }
#pragma unroll
    for (int i = 0; i < TM; i++) {
        int m = m0 + ty * TM + i;
        if (m >= M) continue;
#pragma unroll
        for (int j = 0; j < TN / 2; j++) {
            union { unsigned long long u; float f[2]; } cv;
            cv.u = acc2[i][j];
            int n = n0 + tx * TN + 2 * j;
            if (n + 1 < N) *(float2*)(C + (long long)m * ldc + n) = make_float2(cv.f[0], cv.f[1]);
            else if (n < N) C[(long long)m * ldc + n] = cv.f[0];
        }
    }
}

// ====== fused recurrent GEMM + LSTM cell (R6/R7 64x64 single-buffer) =======
// BM=BN=64, TM=TN=4; grid (29, 4, 2) = 232 blocks.
__global__ __launch_bounds__(256) void lstm_rec(
    const float* __restrict__ h_in, const float* __restrict__ Whh,
    const float* __restrict__ XW, const float* __restrict__ bs,
    float* __restrict__ h_out, float* __restrict__ c,
    float* __restrict__ y, int step, int finalsBase)
{
    constexpr int BK = 16, KV = 4;
    __shared__ float As[BK][68];
    __shared__ float Bs[BK][68];
    const int dir = blockIdx.z;
    const float* A  = h_in + (long long)dir * Bc * HP;
    const float* Bm = Whh + (long long)dir * NP * HP;
    const int tid = threadIdx.x, tx = tid % 16, ty = tid / 16;
    const int m0 = blockIdx.y * 64, n0 = blockIdx.x * 64;
    const int T = HP / BK;
    const int r = tid / KV, kv = tid % KV;

    float4 aR = *(const float4*)(A + (long long)(m0 + r) * HP + kv * 4);
    float4 bR = *(const float4*)(Bm + (long long)(n0 + r) * HP + kv * 4);

    unsigned long long acc2[4][2];
#pragma unroll
    for (int i = 0; i < 4; i++) { acc2[i][0] = 0ull; acc2[i][1] = 0ull; }

    for (int t = 0; t < T; t++) {
        As[kv * 4 + 0][r] = aR.x; As[kv * 4 + 1][r] = aR.y;
        As[kv * 4 + 2][r] = aR.z; As[kv * 4 + 3][r] = aR.w;
        Bs[kv * 4 + 0][r] = bR.x; Bs[kv * 4 + 1][r] = bR.y;
        Bs[kv * 4 + 2][r] = bR.z; Bs[kv * 4 + 3][r] = bR.w;
        __syncthreads();
        if (t + 1 < T) {
            int gk = (t + 1) * BK + kv * 4;
            aR = *(const float4*)(A + (long long)(m0 + r) * HP + gk);
            bR = *(const float4*)(Bm + (long long)(n0 + r) * HP + gk);
        }
#pragma unroll
        for (int kk = 0; kk < BK; kk++) {
            float4 raV = *(const float4*)&As[kk][ty * 4];
            const float* ra = (const float*)&raV;
            float4 rbV = *(const float4*)&Bs[kk][tx * 4];
            const unsigned long long* rb = (const unsigned long long*)&rbV;
#pragma unroll
            for (int i = 0; i < 4; i++) {
                unsigned long long a2;
                unsigned au = __float_as_uint(ra[i]);
                asm("mov.b64 %0,{%1,%1};" : "=l"(a2) : "r"(au));
                asm("fma.rn.f32x2 %0,%1,%2,%3;" : "=l"(acc2[i][0]) : "l"(a2), "l"(rb[0]), "l"(acc2[i][0]));
                asm("fma.rn.f32x2 %0,%1,%2,%3;" : "=l"(acc2[i][1]) : "l"(a2), "l"(rb[1]), "l"(acc2[i][1]));
            }
        }
        __syncthreads();
    }

    // epilogue: columns n0+tx*4 .. +3 = 4 gates of unit jj
    const int jj = (n0 >> 2) + tx;
    if (jj >= Hc) return;
    const int tstep = dir ? (4 - step) : step;
    const float4 bsv = *(const float4*)(bs + dir * 1800 + 4 * jj);
#pragma unroll
    for (int i = 0; i < 4; i++) {
        int b = m0 + ty * 4 + i;
        union { unsigned long long u; float f[2]; } c0, c1;
        c0.u = acc2[i][0]; c1.u = acc2[i][1];
        const float4 xwv = *(const float4*)(XW + ((long long)(tstep * Bc + b)) * 3600 + dir * 1800 + 4 * jj);
        float gi = c0.f[0] + xwv.x + bsv.x;
        float gf = c0.f[1] + xwv.y + bsv.y;
        float gg = c1.f[0] + xwv.z + bsv.z;
        float go = c1.f[1] + xwv.w + bsv.w;
        int ci = (dir * Bc + b) * Hc + jj;
        float cp = c[ci];
        float cn = sigm(gf) * cp + sigm(gi) * tanhf(gg);
        float hn = sigm(go) * tanhf(cn);
        c[ci] = cn;
        h_out[(dir * Bc + b) * HP + jj] = hn;
        y[((long long)(tstep * Bc + b)) * 900 + dir * Hc + jj] = hn;
        if (step == 4) d_finals[((long long)(finalsBase + dir) * Bc + b) * Hc + jj] = hn;
    }
}

// ============ step 0 (no recurrent term) ===================================
__global__ void lstm_step0(const float* __restrict__ XW, const float* __restrict__ bs,
                           float* __restrict__ h_out, float* __restrict__ c,
                           float* __restrict__ y)
{
    int idx = blockIdx.x * blockDim.x + threadIdx.x;
    if (idx >= 2 * Bc * Hc) return;
    int dir = idx / (Bc * Hc);
    int r = idx - dir * Bc * Hc;
    int b = r / Hc, j = r - (r / Hc) * Hc;
    int t = dir ? 4 : 0;
    const float4 xwv = *(const float4*)(XW + ((long long)(t * Bc + b)) * 3600 + dir * 1800 + 4 * j);
    const float4 bsv = *(const float4*)(bs + dir * 1800 + 4 * j);
    float gi = xwv.x + bsv.x, gg = xwv.z + bsv.z, go = xwv.w + bsv.w;
    float cn = sigm(gi) * tanhf(gg);
    float hn = sigm(go) * tanhf(cn);
    c[(dir * Bc + b) * Hc + j] = cn;
    h_out[(dir * Bc + b) * HP + j] = hn;
    y[((long long)(t * Bc + b)) * 900 + dir * Hc + j] = hn;
}

// ============ prep kernels =================================================
__global__ void prep_small(const float* __restrict__ gcn_w,
                           const float* __restrict__ bih0, const float* __restrict__ bhh0,
                           const float* __restrict__ bih1, const float* __restrict__ bhh1)
{
    int i = blockIdx.x * blockDim.x + threadIdx.x;
    if (i < 20000) {
        int op = i / 100, k = i - op * 100;
        d_W2[op * 100 + k] = gcn_w[(op % 100) * 200 + (op / 100) * 100 + k];
    } else if (i < 23600) {
        int r = i - 20000, dir = r / 1800, q = r - dir * 1800;
        int j = q >> 2, g = q & 3, s = dir * 1800 + g * 450 + j;
        d_bs0[dir * 1800 + q] = bih0[s] + bhh0[s];
    } else if (i < 27200) {
        int r = i - 23600, dir = r / 1800, q = r - dir * 1800;
        int j = q >> 2, g = q & 3, s = dir * 1800 + g * 450 + j;
        d_bs1[dir * 1800 + q] = bih1[s] + bhh1[s];
    } else if (i < 27200 + 2 * Bc * HP) {
        d_hA[i - 27200] = 0.0f;
    } else if (i < 27200 + 4 * Bc * HP) {
        d_hB[i - 27200 - 2 * Bc * HP] = 0.0f;
    }
}

__global__ void prep_ih(const float* __restrict__ Wih0, const float* __restrict__ Wih1)
{
    int i = blockIdx.x * blockDim.x + threadIdx.x;
    if (i < 720000) {
        int dir = i / 360000, rem = i - dir * 360000;
        int q = rem / 200, k = rem - q * 200;
        int j = q >> 2, g = q & 3;
        d_Wih0i[i] = Wih0[dir * 360000 + (g * 450 + j) * 200 + k];
    } else if (i < 720000 + 3240000) {
        int i2 = i - 720000;
        int dir = i2 / 1620000, rem = i2 - dir * 1620000;
        int q = rem / 900, k = rem - q * 900;
        int j = q >> 2, g = q & 3;
        d_Wih1i[i2] = Wih1[dir * 1620000 + (g * 450 + j) * 900 + k];
    }
}

__global__ void prep_hh(const float* __restrict__ Whh0, const float* __restrict__ Whh1)
{
    int i = blockIdx.x * blockDim.x + threadIdx.x;
    const int PER = 2 * NP * HP;
    if (i >= 2 * PER) return;
    int layer = i / PER, i2 = i - layer * PER;
    int dir = i2 / (NP * HP), rem = i2 - dir * (NP * HP);
    int r = rem / HP, k = rem - r * HP;
    float v = 0.0f;
    if (r < 1800 && k < 450) {
        int j = r >> 2, g = r & 3;
        const float* src = layer ? Whh1 : Whh0;
        v = src[dir * 810000 + (g * 450 + j) * 450 + k];
    }
    (layer ? d_Whh1i : d_Whh0i)[i2] = v;
}

// ============ neighbor encoder (1 block per row) ===========================
__global__ __launch_bounds__(256) void encoder_kernel(
    const int* __restrict__ lc, const int* __restrict__ rc,
    const float* __restrict__ emb,
    const float* __restrict__ gcn_wb, const float* __restrict__ gcn_b,
    const float* __restrict__ attn_w, const float* __restrict__ attn_wb,
    const float* __restrict__ gate_w, const float* __restrict__ gate_wb,
    const float* __restrict__ gate_b)
{
    extern __shared__ __align__(16) float outbuf[];
    __shared__ float logits[Mc], wts[Mc], bias[Dc], aw[Dc], gw[Dc], oattn[Dc], red[256], gsc;
    const int n = blockIdx.x;
    const int f = n / (2 * Bc);
    const int rem = n - f * 2 * Bc;
    const int s = rem / Bc, bb = rem - (rem / Bc) * Bc;
    const int* conn = (s == 0 ? lc : rc) + ((long long)(f * Bc + bb) * Mc) * 3;
    const int tid = threadIdx.x;
    if (tid < Dc) { bias[tid] = gcn_wb[tid] + gcn_b[tid]; aw[tid] = attn_w[tid]; gw[tid] = gate_w[tid]; }
    __syncthreads();
    const float awb = attn_wb[0];

    for (int m = tid; m < Mc; m += 256) {
        int i1 = conn[m * 3 + 1], i2 = conn[m * 3 + 2];
        const float4* p1 = (const float4*)(d_P + (long long)i1 * 200);
        const float4* p2 = (const float4*)(d_P + (long long)i2 * 200 + 100);
        float4* orow = (float4*)(outbuf + m * Dc);
        float lg = 0.0f;
#pragma unroll 25
        for (int q = 0; q < 25; q++) {
            float4 a = p1[q], b4 = p2[q];
            float v0 = a.x + b4.x + bias[4 * q + 0];
            float v1 = a.y + b4.y + bias[4 * q + 1];
            float v2 = a.z + b4.z + bias[4 * q + 2];
            float v3 = a.w + b4.w + bias[4 * q + 3];
            v0 = v0 >= 0.f ? v0 : 0.01f * v0;
            v1 = v1 >= 0.f ? v1 : 0.01f * v1;
            v2 = v2 >= 0.f ? v2 : 0.01f * v2;
            v3 = v3 >= 0.f ? v3 : 0.01f * v3;
            float4 o; o.x = v0; o.y = v1; o.z = v2; o.w = v3;
            orow[q] = o;
            lg += v0 * aw[4 * q] + v1 * aw[4 * q + 1] + v2 * aw[4 * q + 2] + v3 * aw[4 * q + 3];
        }
        logits[m] = lg + awb;
    }
    __syncthreads();

    float lm = -1e30f;
    for (int m = tid; m < Mc; m += 256) lm = fmaxf(lm, logits[m]);
    red[tid] = lm; __syncthreads();
    for (int st = 128; st > 0; st >>= 1) { if (tid < st) red[tid] = fmaxf(red[tid], red[tid + st]); __syncthreads(); }
    float mx = red[0]; __syncthreads();
    float ls = 0.0f;
    for (int m = tid; m < Mc; m += 256) { float e = expf(logits[m] - mx); wts[m] = e; ls += e; }
    red[tid] = ls; __syncthreads();
    for (int st = 128; st > 0; st >>= 1) { if (tid < st) red[tid] += red[tid + st]; __syncthreads(); }
    float inv = 1.0f / red[0]; __syncthreads();
    for (int m = tid; m < Mc; m += 256) wts[m] *= inv;
    __syncthreads();

    for (int o = tid; o < Dc; o += 256) {
        float acc = 0.0f;
        for (int m = 0; m < Mc; m++) acc += outbuf[m * Dc + o] * wts[m];
        oattn[o] = acc;
    }
    __syncthreads();

    float gd = 0.0f;
    for (int o = tid; o < Dc; o += 256) gd += oattn[o] * gw[o];
    red[tid] = gd; __syncthreads();
    for (int st = 128; st > 0; st >>= 1) { if (tid < st) red[tid] += red[tid + st]; __syncthreads(); }
    if (tid == 0) gsc = sigm(red[0] + gate_wb[0] + gate_b[0]);
    __syncthreads();
    float g = gsc;
    int self_idx = conn[0];
    const float* se = emb + (long long)self_idx * Dc;
    for (int o = tid; o < Dc; o += 256)
        d_x[((long long)f * Bc + bb) * 200 + s * Dc + o] = oattn[o] * g + se[o] * (1.0f - g);
}

// ============ attention over LSTM output + rel projection ==================
__global__ __launch_bounds__(256) void attn_kernel(const float* __restrict__ out_w,
                                                   const float* __restrict__ out_b)
{
    __shared__ float O[FEWc * 900];
    __shared__ float Hs[1800], ctx[1800], lg[10], awt[10];
    const int b = blockIdx.x, tid = threadIdx.x;
    for (int i = tid; i < FEWc * 900; i += 256) {
        int t = i / 900, h2 = i - t * 900;
        O[i] = d_y1[((long long)t * Bc + b) * 900 + h2];
    }
    for (int i = tid; i < 1800; i += 256) Hs[i] = d_finals[(long long)b * 1800 + i];
    if (tid < 10) lg[tid] = 0.0f;
    __syncthreads();

    float part[10];
#pragma unroll
    for (int q = 0; q < 10; q++) part[q] = 0.0f;
    for (int h2 = tid; h2 < 900; h2 += 256) {
        float hl0 = Hs[2 * h2], hl1 = Hs[2 * h2 + 1];
#pragma unroll
        for (int t = 0; t < 5; t++) {
            float ov = O[t * 900 + h2];
            part[2 * t]     += ov * hl0;
            part[2 * t + 1] += ov * hl1;
        }
    }
#pragma unroll
    for (int q = 0; q < 10; q++) {
        float v = warpred(part[q]);
        if ((tid & 31) == 0) atomicAdd(&lg[q], v);
    }
    __syncthreads();
    if (tid < 2) {
        int l = tid;
        float mxv = -1e30f;
        for (int t = 0; t < 5; t++) mxv = fmaxf(mxv, lg[t * 2 + l]);
        float sm = 0.0f, e[5];
        for (int t = 0; t < 5; t++) { e[t] = expf(lg[t * 2 + l] - mxv); sm += e[t]; }
        for (int t = 0; t < 5; t++) awt[t * 2 + l] = e[t] / sm;
    }
    __syncthreads();
    for (int i = tid; i < 1800; i += 256) {
        int h2 = i >> 1, l = i & 1;
        float acc = 0.0f;
#pragma unroll
        for (int t = 0; t < 5; t++) acc += O[t * 900 + h2] * awt[t * 2 + l];
        ctx[i] = acc;
    }
    __syncthreads();
    int w = tid >> 5, lane = tid & 31;
    for (int o = w; o < Dc; o += 8) {
        float acc = 0.0f;
        for (int k = lane; k < 1800; k += 32) acc += ctx[k] * out_w[(long long)o * 1800 + k];
        acc = warpred(acc);
        if (lane == 0) d_rel[(long long)b * Dc + o] = acc + out_b[o];
    }
}

// ============ meta gradient ================================================
__global__ void meta_kernel(const float* __restrict__ support, const float* __restrict__ sneg,
                            const float* __restrict__ normv)
{
    int b = blockIdx.x, lane = threadIdx.x;
    float r4[4], n4[4], g4[4] = {0, 0, 0, 0};
#pragma unroll
    for (int i = 0; i < 4; i++) {
        int o = lane + 32 * i;
        r4[i] = (o < Dc) ? d_rel[b * Dc + o] : 0.0f;
        n4[i] = (o < Dc) ? normv[(long long)b * Dc + o] : 0.0f;
    }
    for (int k = 0; k < 5; k++) {
        const float* hp = support + ((long long)(b * 5 + k) * 2) * Dc;
        const float* tp = hp + Dc;
        const float* hn = sneg + ((long long)(b * 5 + k) * 2) * Dc;
        const float* tn = hn + Dc;
        float up[4], un[4], ap = 0.0f, an = 0.0f;
#pragma unroll
        for (int i = 0; i < 4; i++) {
            int o = lane + 32 * i;
            up[i] = (o < Dc) ? hp[o] - tp[o] : 0.0f;
            un[i] = (o < Dc) ? hn[o] - tn[o] : 0.0f;
            ap += up[i] * n4[i];
            an += un[i] * n4[i];
        }
        ap = warpred(ap); an = warpred(an);
        float dp4[4], dn4[4], sp = 0.0f, sn = 0.0f;
#pragma unroll
        for (int i = 0; i < 4; i++) {
            dp4[i] = up[i] + r4[i] - ap * n4[i];
            dn4[i] = un[i] + r4[i] - an * n4[i];
            sp += dp4[i] * dp4[i];
            sn += dn4[i] * dn4[i];
        }
        sp = warpred(sp); sn = warpred(sn);
        float Dp = sqrtf(sp), Dn = sqrtf(sn);
        if (1.0f + Dp - Dn > 0.0f) {
            float ip = 1.0f / Dp, inn = 1.0f / Dn;
#pragma unroll
            for (int i = 0; i < 4; i++) g4[i] += dp4[i] * ip - dn4[i] * inn;
        }
    }
#pragma unroll
    for (int i = 0; i < 4; i++) {
        int o = lane + 32 * i;
        if (o < Dc) {
            float g = g4[i] * (1.0f / 1280.0f);
            d_relq[b * Dc + o]  = r4[i] - 5.0f * g;
            d_normq[b * Dc + o] = n4[i] - 5.0f * g;
        }
    }
}

// ============ final scoring ================================================
__global__ __launch_bounds__(256) void score_kernel(const float* __restrict__ query,
                                                    const float* __restrict__ negative,
                                                    float* __restrict__ out)
{
    __shared__ float rq[Dc], nq[Dc];
    int b = blockIdx.y, tid = threadIdx.x;
    if (tid < Dc) { rq[tid] = d_relq[b * Dc + tid]; nq[tid] = d_normq[b * Dc + tid]; }
    __syncthreads();
    int w = tid >> 5, lane = tid & 31;
    int q = blockIdx.x * 8 + w;
    if (q >= 522) return;
    const float* hp;
    if (q < 10) hp = query + ((long long)(b * 10 + q) * 2) * Dc;
    else        hp = negative + ((long long)(b * 512 + (q - 10)) * 2) * Dc;
    const float* tp = hp + Dc;
    float u[4], rr[4], nn2[4], al = 0.0f;
#pragma unroll
    for (int i = 0; i < 4; i++) {
        int o = lane + 32 * i;
        if (o < Dc) { u[i] = hp[o] - tp[o]; rr[i] = rq[o]; nn2[i] = nq[o]; }
        else        { u[i] = 0.0f; rr[i] = 0.0f; nn2[i] = 0.0f; }
        al += u[i] * nn2[i];
    }
    al = warpred(al);
    float s = 0.0f;
#pragma unroll
    for (int i = 0; i < 4; i++) {
        float d = u[i] + rr[i] - al * nn2[i];
        s += d * d;
    }
    s = warpred(s);
    if (lane == 0) {
        float sc = -sqrtf(s);
        if (q < 10) out[b * 10 + q] = sc;
        else        out[2560 + (long long)b * 512 + (q - 10)] = sc;
    }
}

// ============ host launcher ================================================
extern "C" void kernel_launch(void* const* d_in, const int* in_sizes, int n_in,
                              void* d_out, int out_size)
{
    const float* support  = (const float*)d_in[0];
    const float* sneg     = (const float*)d_in[1];
    const float* query    = (const float*)d_in[2];
    const float* negative = (const float*)d_in[3];
    const float* normv    = (const float*)d_in[4];
    const int*   leftc    = (const int*)d_in[5];
    const int*   rightc   = (const int*)d_in[6];
    const float* emb      = (const float*)d_in[7];
    const float* gcn_w    = (const float*)d_in[8];
    const float* gcn_wb   = (const float*)d_in[9];
    const float* gcn_b    = (const float*)d_in[10];
    const float* attn_w   = (const float*)d_in[11];
    const float* attn_wb  = (const float*)d_in[12];
    const float* gate_w   = (const float*)d_in[13];
    const float* gate_wb  = (const float*)d_in[14];
    const float* gate_b   = (const float*)d_in[15];
    const float* Wih0     = (const float*)d_in[16];
    const float* Whh0     = (const float*)d_in[17];
    const float* bih0     = (const float*)d_in[18];
    const float* bhh0     = (const float*)d_in[19];
    const float* Wih1     = (const float*)d_in[20];
    const float* Whh1     = (const float*)d_in[21];
    const float* bih1     = (const float*)d_in[22];
    const float* bhh1     = (const float*)d_in[23];
    const float* out_w    = (const float*)d_in[24];
    const float* out_b    = (const float*)d_in[25];
    float* out = (float*)d_out;

    float *P, *W2, *X, *XW0v, *XW1v, *Y0, *Y1, *HA, *HB, *Cst;
    float *Wih0i, *Wih1i, *Whh0i, *Whh1i, *BS0, *BS1;
    cudaGetSymbolAddress((void**)&P,     d_P);
    cudaGetSymbolAddress((void**)&W2,    d_W2);
    cudaGetSymbolAddress((void**)&X,     d_x);
    cudaGetSymbolAddress((void**)&XW0v,  d_XW0);
    cudaGetSymbolAddress((void**)&XW1v,  d_XW1);
    cudaGetSymbolAddress((void**)&Y0,    d_y0);
    cudaGetSymbolAddress((void**)&Y1,    d_y1);
    cudaGetSymbolAddress((void**)&HA,    d_hA);
    cudaGetSymbolAddress((void**)&HB,    d_hB);
    cudaGetSymbolAddress((void**)&Cst,   d_cst);
    cudaGetSymbolAddress((void**)&Wih0i, d_Wih0i);
    cudaGetSymbolAddress((void**)&Wih1i, d_Wih1i);
    cudaGetSymbolAddress((void**)&Whh0i, d_Whh0i);
    cudaGetSymbolAddress((void**)&Whh1i, d_Whh1i);
    cudaGetSymbolAddress((void**)&BS0,   d_bs0);
    cudaGetSymbolAddress((void**)&BS1,   d_bs1);

    int prepN = 27200 + 4 * Bc * HP;
    prep_small<<<(prepN + 255) / 256, 256>>>(gcn_w, bih0, bhh0, bih1, bhh1);
    prep_ih<<<(3960000 + 255) / 256, 256>>>(Wih0, Wih1);
    prep_hh<<<(2 * 2 * NP * HP + 255) / 256, 256>>>(Whh0, Whh1);

    // P = emb @ W2^T
    {
        dim3 g(2, (NSYMc + 1 + 127) / 128, 1);
        sgemm_nt<128, 128, 16, 8, 8, true><<<g, 256>>>(NSYMc + 1, 200, 100, 7,
            emb, 100, 0, W2, 100, 0, P, 200, 0);
    }
    cudaFuncSetAttribute(encoder_kernel, cudaFuncAttributeMaxDynamicSharedMemorySize,
                         Mc * Dc * (int)sizeof(float));
    encoder_kernel<<<FEWc * 2 * Bc, 256, Mc * Dc * sizeof(float)>>>(
        leftc, rightc, emb, gcn_wb, gcn_b, attn_w, attn_wb, gate_w, gate_wb, gate_b);

    dim3 gbig(15, 10, 2);
    dim3 grec(29, 4, 2);

    // layer 0
    sgemm_nt<128, 128, 16, 8, 8, true><<<gbig, 256>>>(FEWc * Bc, 1800, 200, 13,
        X, 200, 0, Wih0i, 200, (long long)1800 * 200, XW0v, 3600, 1800);
    lstm_step0<<<900, 256>>>(XW0v, BS0, HA, Cst, Y0);
    float* hbuf[2] = {HA, HB};
    for (int s = 1; s < 5; s++)
        lstm_rec<<<grec, 256>>>(hbuf[(s + 1) & 1], Whh0i, XW0v, BS0, hbuf[s & 1], Cst, Y0, s, 0);
    // layer 1
    sgemm_nt<128, 128, 16, 8, 8, true><<<gbig, 256>>>(FEWc * Bc, 1800, 900, 57,
        Y0, 900, 0, Wih1i, 900, (long long)1800 * 900, XW1v, 3600, 1800);
    lstm_step0<<<900, 256>>>(XW1v, BS1, HA, Cst, Y1);
    for (int s = 1; s < 5; s++)
        lstm_rec<<<grec, 256>>>(hbuf[(s + 1) & 1], Whh1i, XW1v, BS1, hbuf[s & 1], Cst, Y1, s, 2);

    attn_kernel<<<Bc, 256>>>(out_w, out_b);
    meta_kernel<<<Bc, 32>>>(support, sneg, normv);
    score_kernel<<<dim3((522 + 7) / 8, Bc), 256>>>(query, negative, out);
}